// round 1
// baseline (speedup 1.0000x reference)
#include <cuda_runtime.h>
#include <cuda_bf16.h>
#include <cstdint>

#define NGROUP 1024
#define MAXB   64

// Per-batch group start offsets: g_start[b*(NGROUP+1) + g] = first token index s
// with segment_ids[b,s] >= g. Sentinel at index NGROUP = S.
__device__ int g_start[MAXB * (NGROUP + 1)];

// ---------------------------------------------------------------------------
// Kernel 1: compute group boundaries from the sorted segment ids.
// One thread per token; boundary threads fill the start table for the groups
// they open. Total writes = B*(NGROUP+1), no atomics.
// ---------------------------------------------------------------------------
__global__ void boundaries_kernel(const int* __restrict__ seg, int B, int S) {
    int idx = blockIdx.x * blockDim.x + threadIdx.x;
    if (idx >= B * S) return;
    int b = idx / S;
    int s = idx - b * S;
    const int* row = seg + (size_t)b * S;
    int* st = g_start + b * (NGROUP + 1);
    int id = row[s];
    if (s == 0) {
        // groups 0..id all start at 0
        for (int g = 0; g <= id; ++g) st[g] = 0;
    } else {
        int prev = row[s - 1];
        // groups (prev, id] start here (empty groups in the gap get start=s too,
        // making their [start, next_start) range empty)
        for (int g = prev + 1; g <= id; ++g) st[g] = s;
    }
    if (s == S - 1) {
        for (int g = id + 1; g <= NGROUP; ++g) st[g] = S;
    }
}

// ---------------------------------------------------------------------------
// Kernel 2: mean-pool each (b, g) range. One CTA per (g, b). Threads stride
// the H dimension in float4; inner loop walks the contiguous token slab.
// Hv = H/4.
// ---------------------------------------------------------------------------
__global__ __launch_bounds__(128)
void pool_kernel(const float4* __restrict__ feats, float4* __restrict__ out,
                 float* __restrict__ counts_out, int S, int Hv) {
    int g = blockIdx.x;
    int b = blockIdx.y;
    const int* st = g_start + b * (NGROUP + 1);
    int s0 = st[g];
    int s1 = st[g + 1];
    int cnt = s1 - s0;
    float inv = (cnt > 0) ? (1.0f / (float)cnt) : 0.0f;

    const float4* base = feats + ((size_t)b * S + s0) * Hv;
    float4* o = out + ((size_t)b * NGROUP + g) * Hv;

    for (int v = threadIdx.x; v < Hv; v += blockDim.x) {
        float acc_x = 0.f, acc_y = 0.f, acc_z = 0.f, acc_w = 0.f;
        const float4* p = base + v;
        #pragma unroll 4
        for (int t = 0; t < cnt; ++t) {
            float4 x = p[(size_t)t * Hv];
            acc_x += x.x; acc_y += x.y; acc_z += x.z; acc_w += x.w;
        }
        float4 r;
        r.x = acc_x * inv; r.y = acc_y * inv; r.z = acc_z * inv; r.w = acc_w * inv;
        o[v] = r;
    }

    if (counts_out != nullptr && threadIdx.x == 0) {
        counts_out[(size_t)b * NGROUP + g] = (float)cnt;
    }
}

// ---------------------------------------------------------------------------
extern "C" void kernel_launch(void* const* d_in, const int* in_sizes, int n_in,
                              void* d_out, int out_size) {
    const float* feats = (const float*)d_in[0];
    const int*   seg   = (const int*)d_in[1];
    float* out = (float*)d_out;

    const int n_feat = in_sizes[0];   // B*S*H
    const int n_seg  = in_sizes[1];   // B*S
    const int H = n_feat / n_seg;

    // Does the output buffer include the counts tail [B,G]?
    int B;
    bool has_counts;
    if (out_size % (NGROUP * (H + 1)) == 0 &&
        (out_size / (NGROUP * (H + 1))) * n_seg ==
        (out_size / (NGROUP * (H + 1))) * n_seg /* keep B consistent below */) {
        B = out_size / (NGROUP * (H + 1));
        has_counts = true;
        if (B <= 0 || n_seg % B != 0) { // fallback: grouped-only layout
            B = out_size / (NGROUP * H);
            has_counts = false;
        }
    } else {
        B = out_size / (NGROUP * H);
        has_counts = false;
    }
    const int S = n_seg / B;
    const int Hv = H / 4;

    float* counts_out = has_counts ? out + (size_t)B * NGROUP * H : nullptr;

    // Kernel 1: boundaries
    {
        int total = B * S;
        int threads = 256;
        int blocks = (total + threads - 1) / threads;
        boundaries_kernel<<<blocks, threads>>>(seg, B, S);
    }

    // Kernel 2: pooling
    {
        dim3 grid(NGROUP, B);
        pool_kernel<<<grid, 128>>>((const float4*)feats, (float4*)out,
                                   counts_out, S, Hv);
    }
}